// round 3
// baseline (speedup 1.0000x reference)
#include <cuda_runtime.h>
#include <cstdint>

// WindowAttention: B=4096, N=64 tokens, C=128. One CTA/window, 256 threads.
// 2x4 warp grid, 32x32 warp tiles, mma.m16n8k8 tf32.
// Packed-pair smem layouts -> every MMA fragment is one conflict-free LDS.64.

#define PA  136     // packed-A pitch (X, Q/O, K): {M[r][k],M[r][k+4]} pairs
#define PSS 72      // packed-A pitch for S (64 cols)
#define SW  514     // W packed-B nBlk stride (16 kg * 32 + 2)
#define SV  258     // V packed-B nBlk stride (8 kg * 32 + 2)

#define OFF_X  0
#define OFF_Q  (64*PA)            // 8704   (reused for O)
#define OFF_K  (2*64*PA)          // 17408
#define OFF_V  (3*64*PA)          // 26112
#define OFF_W  (OFF_V + 32*SV)    // 34368
#define OFF_S  OFF_W              // S aliases W (dead in between)
#define OFF_PM (OFF_W + 64*PSS)   // softmax partials, inside W region
#define SMEM_FLOATS (OFF_W + 32*SW)   // 50816
#define SMEM_BYTES  (SMEM_FLOATS * 4) // 203264

__device__ __forceinline__ float tf32f(float x) {
    uint32_t u;
    asm("cvt.rna.tf32.f32 %0, %1;" : "=r"(u) : "f"(x));
    return __uint_as_float(u);
}
__device__ __forceinline__ uint32_t u32(float x) { return __float_as_uint(x); }

__device__ __forceinline__ void mma8(float acc[4],
                                     uint32_t a0, uint32_t a1, uint32_t a2, uint32_t a3,
                                     uint32_t b0, uint32_t b1) {
    asm volatile(
        "mma.sync.aligned.m16n8k8.row.col.f32.tf32.tf32.f32 "
        "{%0,%1,%2,%3}, {%4,%5,%6,%7}, {%8,%9}, {%0,%1,%2,%3};\n"
        : "+f"(acc[0]), "+f"(acc[1]), "+f"(acc[2]), "+f"(acc[3])
        : "r"(a0), "r"(a1), "r"(a2), "r"(a3), "r"(b0), "r"(b1));
}

__device__ __forceinline__ void bargrp(int id) {
    asm volatile("bar.sync %0, 128;" :: "r"(id) : "memory");
}

// store 2x2 output micro-frag into packed-A layout
__device__ __forceinline__ void stPackedA(float* base, int pitch, int r0, int j,
                                          float v0, float v1, float v2, float v3) {
    int kg8 = (j >> 3) * 8;
    int p0 = 2 * (j & 3) + ((j >> 2) & 1);
    int p1 = 2 * ((j + 1) & 3) + (((j + 1) >> 2) & 1);
    float* b0 = base + r0 * pitch + kg8;
    b0[p0] = v0; b0[p1] = v1;
    float* b1 = b0 + 8 * pitch;
    b1[p0] = v2; b1[p1] = v3;
}

// gmem [128 x ncols] (row stride `stride`) -> packed-B in Wp (16 kg, stride SW)
__device__ __forceinline__ void stageW(const float* __restrict__ src, int stride,
                                       float* Wp, int tid) {
    int nq = tid & 31;           // lanes -> consecutive columns (coalesced LDG)
    int v  = tid >> 5;
    #pragma unroll
    for (int s = 0; s < 8; ++s) {
        int vv = v + s * 8;      // 0..63
        int tt = vv & 3;
        int kg = vv >> 2;        // 0..15
        const float* p0 = src + (8 * kg + tt) * stride + nq * 4;
        float4 w0 = *(const float4*)p0;
        float4 w1 = *(const float4*)(p0 + 4 * stride);
        float* d = Wp + nq * SW + kg * 32 + 2 * tt;
        *(float2*)(d + 0)  = make_float2(tf32f(w0.x), tf32f(w1.x));
        *(float2*)(d + 8)  = make_float2(tf32f(w0.y), tf32f(w1.y));
        *(float2*)(d + 16) = make_float2(tf32f(w0.z), tf32f(w1.z));
        *(float2*)(d + 24) = make_float2(tf32f(w0.w), tf32f(w1.w));
    }
}

__global__ void __launch_bounds__(256, 1)
win_attn_kernel(const float* __restrict__ x,
                const float* __restrict__ wqkv,
                const float* __restrict__ bqkv,
                const float* __restrict__ wproj,
                const float* __restrict__ bproj,
                float* __restrict__ out)
{
    extern __shared__ float smem[];
    float* Xs = smem + OFF_X;
    float* Qs = smem + OFF_Q;   // O later
    float* Ks = smem + OFF_K;
    float* Vp = smem + OFF_V;
    float* Wp = smem + OFF_W;
    float* Ss = smem + OFF_S;
    float* Pm = smem + OFF_PM;

    const int tid   = threadIdx.x;
    const int warp  = tid >> 5;
    const int lane  = tid & 31;
    const int g     = lane >> 2;
    const int t     = lane & 3;
    const int warpM = warp & 1;
    const int warpN = warp >> 1;        // 0..3
    const int mrow  = warpM * 32;
    const int nc32  = warpN * 32;

    const float* xw = x + (size_t)blockIdx.x * 64 * 128;

    // ---------- prologue: X -> packed-A, wqkv chunk0 -> packed-B ----------
    #pragma unroll
    for (int s = 0; s < 4; ++s) {
        int i  = tid + s * 256;
        int kg = i & 15;
        int r  = i >> 4;
        const float* p = xw + r * 128 + kg * 8;
        float4 u0 = *(const float4*)p;
        float4 u1 = *(const float4*)(p + 4);
        float* d = Xs + r * PA + kg * 8;
        *(float4*)(d)     = make_float4(tf32f(u0.x), tf32f(u1.x), tf32f(u0.y), tf32f(u1.y));
        *(float4*)(d + 4) = make_float4(tf32f(u0.z), tf32f(u1.z), tf32f(u0.w), tf32f(u1.w));
    }
    stageW(wqkv, 384, Wp, tid);
    __syncthreads();

    // B-fragment thread pointer pieces (packed-B)
    const int bThrOff = (g >> 2) * SW + (g & 3) * 8 + 2 * t;
    const float* BthrW = Wp + (nc32 >> 2) * SW + bThrOff;

    // ============ GEMM1: QKV = X @ Wqkv + b, 3 chunks (Q, K, V) ============
    for (int c = 0; c < 3; ++c) {
        float acc[2][4][4];
        #pragma unroll
        for (int m = 0; m < 2; ++m)
            #pragma unroll
            for (int n = 0; n < 4; ++n)
                acc[m][n][0] = acc[m][n][1] = acc[m][n][2] = acc[m][n][3] = 0.f;

        const float* Ar = Xs + (mrow + g) * PA + 2 * t;
        #pragma unroll
        for (int kg = 0; kg < 16; ++kg) {
            float2 aL0 = *(const float2*)(Ar + kg * 8);
            float2 aH0 = *(const float2*)(Ar + 8 * PA + kg * 8);
            float2 aL1 = *(const float2*)(Ar + 16 * PA + kg * 8);
            float2 aH1 = *(const float2*)(Ar + 24 * PA + kg * 8);
            #pragma unroll
            for (int nt = 0; nt < 4; ++nt) {
                float2 b = *(const float2*)(BthrW + nt * (2 * SW) + kg * 32);
                mma8(acc[0][nt], u32(aL0.x), u32(aH0.x), u32(aL0.y), u32(aH0.y), u32(b.x), u32(b.y));
                mma8(acc[1][nt], u32(aL1.x), u32(aH1.x), u32(aL1.y), u32(aH1.y), u32(b.x), u32(b.y));
            }
        }

        // epilogue: +bias, tf32-round, scatter
        #pragma unroll
        for (int m = 0; m < 2; ++m) {
            int r0 = mrow + m * 16 + g;
            #pragma unroll
            for (int nt = 0; nt < 4; ++nt) {
                int j  = nc32 + nt * 8 + 2 * t;       // local col in chunk
                float b0 = __ldg(bqkv + c * 128 + j);
                float b1 = __ldg(bqkv + c * 128 + j + 1);
                float v0 = tf32f(acc[m][nt][0] + b0);
                float v1 = tf32f(acc[m][nt][1] + b1);
                float v2 = tf32f(acc[m][nt][2] + b0);
                float v3 = tf32f(acc[m][nt][3] + b1);
                if (c == 0)      stPackedA(Qs, PA, r0, j, v0, v1, v2, v3);
                else if (c == 1) stPackedA(Ks, PA, r0, j, v0, v1, v2, v3);
                else {
                    // V -> packed-B: element (token r, channel ch)
                    Vp[(j >> 2) * SV + (r0 >> 3) * 32 + (j & 3) * 8 + 2 * (r0 & 3) + ((r0 >> 2) & 1)]           = v0;
                    Vp[((j + 1) >> 2) * SV + (r0 >> 3) * 32 + ((j + 1) & 3) * 8 + 2 * (r0 & 3) + ((r0 >> 2) & 1)] = v1;
                    int r1 = r0 + 8;
                    Vp[(j >> 2) * SV + (r1 >> 3) * 32 + (j & 3) * 8 + 2 * (r1 & 3) + ((r1 >> 2) & 1)]           = v2;
                    Vp[((j + 1) >> 2) * SV + (r1 >> 3) * 32 + ((j + 1) & 3) * 8 + 2 * (r1 & 3) + ((r1 >> 2) & 1)] = v3;
                }
            }
        }
        __syncthreads();          // all warps done reading Wp
        if (c < 2) {
            stageW(wqkv + (c + 1) * 128, 384, Wp, tid);
            __syncthreads();
        }
    }

    // ============ GEMM2: S = Q @ K^T  (32x16 tile per warp) ============
    float sacc[2][2][4];
    #pragma unroll
    for (int m = 0; m < 2; ++m)
        #pragma unroll
        for (int n = 0; n < 2; ++n)
            sacc[m][n][0] = sacc[m][n][1] = sacc[m][n][2] = sacc[m][n][3] = 0.f;

    {
        const float* Ar = Qs + (mrow + g) * PA + 2 * t;
        const float* Br = Ks + (warpN * 16 + g) * PA + 2 * t;
        #pragma unroll
        for (int kg = 0; kg < 16; ++kg) {
            float2 aL0 = *(const float2*)(Ar + kg * 8);
            float2 aH0 = *(const float2*)(Ar + 8 * PA + kg * 8);
            float2 aL1 = *(const float2*)(Ar + 16 * PA + kg * 8);
            float2 aH1 = *(const float2*)(Ar + 24 * PA + kg * 8);
            #pragma unroll
            for (int nt = 0; nt < 2; ++nt) {
                float2 b = *(const float2*)(Br + nt * (8 * PA) + kg * 8);
                mma8(sacc[0][nt], u32(aL0.x), u32(aH0.x), u32(aL0.y), u32(aH0.y), u32(b.x), u32(b.y));
                mma8(sacc[1][nt], u32(aL1.x), u32(aH1.x), u32(aL1.y), u32(aH1.y), u32(b.x), u32(b.y));
            }
        }
    }

    // ---------- softmax: rows span 4 warps with same warpM ----------
    const float scale = 0.08838834764831844f;  // 128^-0.5
    const int bid = 1 + warpM;
    float mx[2][2];
    #pragma unroll
    for (int m = 0; m < 2; ++m) {
        mx[m][0] = -1e30f; mx[m][1] = -1e30f;
        #pragma unroll
        for (int n = 0; n < 2; ++n) {
            #pragma unroll
            for (int q = 0; q < 4; ++q) sacc[m][n][q] *= scale;
            mx[m][0] = fmaxf(mx[m][0], fmaxf(sacc[m][n][0], sacc[m][n][1]));
            mx[m][1] = fmaxf(mx[m][1], fmaxf(sacc[m][n][2], sacc[m][n][3]));
        }
    }
    #pragma unroll
    for (int m = 0; m < 2; ++m)
        #pragma unroll
        for (int h = 0; h < 2; ++h) {
            mx[m][h] = fmaxf(mx[m][h], __shfl_xor_sync(0xffffffffu, mx[m][h], 1));
            mx[m][h] = fmaxf(mx[m][h], __shfl_xor_sync(0xffffffffu, mx[m][h], 2));
        }
    if (t == 0) {
        #pragma unroll
        for (int m = 0; m < 2; ++m)
            #pragma unroll
            for (int h = 0; h < 2; ++h)
                Pm[(mrow + m * 16 + h * 8 + g) * 4 + warpN] = mx[m][h];
    }
    bargrp(bid);
    #pragma unroll
    for (int m = 0; m < 2; ++m)
        #pragma unroll
        for (int h = 0; h < 2; ++h) {
            const float* pr = Pm + (mrow + m * 16 + h * 8 + g) * 4;
            mx[m][h] = fmaxf(fmaxf(pr[0], pr[1]), fmaxf(pr[2], pr[3]));
        }

    float sm[2][2] = {{0.f, 0.f}, {0.f, 0.f}};
    #pragma unroll
    for (int m = 0; m < 2; ++m)
        #pragma unroll
        for (int n = 0; n < 2; ++n) {
            sacc[m][n][0] = __expf(sacc[m][n][0] - mx[m][0]);
            sacc[m][n][1] = __expf(sacc[m][n][1] - mx[m][0]);
            sacc[m][n][2] = __expf(sacc[m][n][2] - mx[m][1]);
            sacc[m][n][3] = __expf(sacc[m][n][3] - mx[m][1]);
            sm[m][0] += sacc[m][n][0] + sacc[m][n][1];
            sm[m][1] += sacc[m][n][2] + sacc[m][n][3];
        }
    #pragma unroll
    for (int m = 0; m < 2; ++m)
        #pragma unroll
        for (int h = 0; h < 2; ++h) {
            sm[m][h] += __shfl_xor_sync(0xffffffffu, sm[m][h], 1);
            sm[m][h] += __shfl_xor_sync(0xffffffffu, sm[m][h], 2);
        }
    if (t == 0) {
        #pragma unroll
        for (int m = 0; m < 2; ++m)
            #pragma unroll
            for (int h = 0; h < 2; ++h)
                Pm[256 + (mrow + m * 16 + h * 8 + g) * 4 + warpN] = sm[m][h];
    }
    bargrp(bid);
    float rs[2][2];
    #pragma unroll
    for (int m = 0; m < 2; ++m)
        #pragma unroll
        for (int h = 0; h < 2; ++h) {
            const float* pr = Pm + 256 + (mrow + m * 16 + h * 8 + g) * 4;
            rs[m][h] = 1.f / (pr[0] + pr[1] + pr[2] + pr[3]);
        }

    // P -> S (packed-A, pitch 72)
    #pragma unroll
    for (int m = 0; m < 2; ++m) {
        int r0 = mrow + m * 16 + g;
        #pragma unroll
        for (int nt = 0; nt < 2; ++nt) {
            int j = warpN * 16 + nt * 8 + 2 * t;
            stPackedA(Ss, PSS, r0, j,
                      tf32f(sacc[m][nt][0] * rs[m][0]),
                      tf32f(sacc[m][nt][1] * rs[m][0]),
                      tf32f(sacc[m][nt][2] * rs[m][1]),
                      tf32f(sacc[m][nt][3] * rs[m][1]));
        }
    }
    bargrp(bid);   // group's S rows complete

    // ============ GEMM3: O = P @ V  (32x32 tile per warp) ============
    float oacc[2][4][4];
    #pragma unroll
    for (int m = 0; m < 2; ++m)
        #pragma unroll
        for (int n = 0; n < 4; ++n)
            oacc[m][n][0] = oacc[m][n][1] = oacc[m][n][2] = oacc[m][n][3] = 0.f;

    {
        const float* Ar = Ss + (mrow + g) * PSS + 2 * t;
        const float* Bthr = Vp + (nc32 >> 2) * SV + (g >> 2) * SV + (g & 3) * 8 + 2 * t;
        #pragma unroll
        for (int kg = 0; kg < 8; ++kg) {
            float2 aL0 = *(const float2*)(Ar + kg * 8);
            float2 aH0 = *(const float2*)(Ar + 8 * PSS + kg * 8);
            float2 aL1 = *(const float2*)(Ar + 16 * PSS + kg * 8);
            float2 aH1 = *(const float2*)(Ar + 24 * PSS + kg * 8);
            #pragma unroll
            for (int nt = 0; nt < 4; ++nt) {
                float2 b = *(const float2*)(Bthr + nt * (2 * SV) + kg * 32);
                mma8(oacc[0][nt], u32(aL0.x), u32(aH0.x), u32(aL0.y), u32(aH0.y), u32(b.x), u32(b.y));
                mma8(oacc[1][nt], u32(aL1.x), u32(aH1.x), u32(aL1.y), u32(aH1.y), u32(b.x), u32(b.y));
            }
        }
    }

    // O -> Qs (packed-A)
    #pragma unroll
    for (int m = 0; m < 2; ++m) {
        int r0 = mrow + m * 16 + g;
        #pragma unroll
        for (int nt = 0; nt < 4; ++nt) {
            int j = nc32 + nt * 8 + 2 * t;
            stPackedA(Qs, PA, r0, j,
                      tf32f(oacc[m][nt][0]), tf32f(oacc[m][nt][1]),
                      tf32f(oacc[m][nt][2]), tf32f(oacc[m][nt][3]));
        }
    }
    __syncthreads();                 // all S reads + O writes done
    stageW(wproj, 128, Wp, tid);     // wproj -> packed-B (overwrites S)
    __syncthreads();

    // ============ GEMM4: out = O @ Wproj + b ============
    float acc[2][4][4];
    #pragma unroll
    for (int m = 0; m < 2; ++m)
        #pragma unroll
        for (int n = 0; n < 4; ++n)
            acc[m][n][0] = acc[m][n][1] = acc[m][n][2] = acc[m][n][3] = 0.f;

    {
        const float* Ar = Qs + (mrow + g) * PA + 2 * t;
        #pragma unroll
        for (int kg = 0; kg < 16; ++kg) {
            float2 aL0 = *(const float2*)(Ar + kg * 8);
            float2 aH0 = *(const float2*)(Ar + 8 * PA + kg * 8);
            float2 aL1 = *(const float2*)(Ar + 16 * PA + kg * 8);
            float2 aH1 = *(const float2*)(Ar + 24 * PA + kg * 8);
            #pragma unroll
            for (int nt = 0; nt < 4; ++nt) {
                float2 b = *(const float2*)(BthrW + nt * (2 * SW) + kg * 32);
                mma8(acc[0][nt], u32(aL0.x), u32(aH0.x), u32(aL0.y), u32(aH0.y), u32(b.x), u32(b.y));
                mma8(acc[1][nt], u32(aL1.x), u32(aH1.x), u32(aL1.y), u32(aH1.y), u32(b.x), u32(b.y));
            }
        }
    }

    float* outw = out + (size_t)blockIdx.x * 64 * 128;
    #pragma unroll
    for (int m = 0; m < 2; ++m) {
        int r0 = mrow + m * 16 + g;
        #pragma unroll
        for (int nt = 0; nt < 4; ++nt) {
            int j = nc32 + nt * 8 + 2 * t;
            float b0 = __ldg(bproj + j);
            float b1 = __ldg(bproj + j + 1);
            *(float2*)(outw + r0 * 128 + j)       = make_float2(acc[m][nt][0] + b0, acc[m][nt][1] + b1);
            *(float2*)(outw + (r0 + 8) * 128 + j) = make_float2(acc[m][nt][2] + b0, acc[m][nt][3] + b1);
        }
    }
}

extern "C" void kernel_launch(void* const* d_in, const int* in_sizes, int n_in,
                              void* d_out, int out_size)
{
    const float* x     = (const float*)d_in[0];
    const float* wqkv  = (const float*)d_in[1];
    const float* bqkv  = (const float*)d_in[2];
    const float* wproj = (const float*)d_in[3];
    const float* bproj = (const float*)d_in[4];
    float* out = (float*)d_out;

    const int nwin = in_sizes[0] / (64 * 128);  // 4096

    cudaFuncSetAttribute(win_attn_kernel,
                         cudaFuncAttributeMaxDynamicSharedMemorySize, SMEM_BYTES);

    win_attn_kernel<<<nwin, 256, SMEM_BYTES>>>(x, wqkv, bqkv, wproj, bproj, out);
}

// round 4
// speedup vs baseline: 1.0670x; 1.0670x over previous
#include <cuda_runtime.h>
#include <cstdint>

// WindowAttention: B=4096 windows, N=64 tokens, C=128 dim, fp32.
// One CTA per window, 512 threads (16 warps): warp = (wr, wc),
//   wr = warp&3 -> 16-row stripe, wc = warp>>2 -> 32-col group.
// mma.m16n8k8 tf32, plain smem layouts (round-2 style), single W buffer
// staged via registers. S + softmax partials alias the W region.

#define PX 132   // X/Q/K pitch: A-frag bank 4g+t (conflict-free)
#define PV 136   // V pitch:     B-frag bank 8t+g (conflict-free)
#define PS 68    // S pitch:     A-frag bank 4g+t
#define PW 136   // W pitch:     B-frag bank 8t+g (128-col chunks)

#define OFF_X  0
#define OFF_Q  (64*PX)
#define OFF_K  (2*64*PX)
#define OFF_V  (3*64*PX)
#define OFF_W  (3*64*PX + 64*PV)   // 34048
#define OFF_S  OFF_W               // S aliases W (dead in between)
#define OFF_PM (OFF_W + 64*PS)     // softmax partials inside W region
#define SMEM_FLOATS (OFF_W + 128*PW)   // 51456
#define SMEM_BYTES  (SMEM_FLOATS * 4)  // 205824

__device__ __forceinline__ float tf32f(float x) {
    uint32_t u;
    asm("cvt.rna.tf32.f32 %0, %1;" : "=r"(u) : "f"(x));
    return __uint_as_float(u);
}

__device__ __forceinline__ void mma8(float acc[4],
                                     uint32_t a0, uint32_t a1, uint32_t a2, uint32_t a3,
                                     uint32_t b0, uint32_t b1) {
    asm volatile(
        "mma.sync.aligned.m16n8k8.row.col.f32.tf32.tf32.f32 "
        "{%0,%1,%2,%3}, {%4,%5,%6,%7}, {%8,%9}, {%0,%1,%2,%3};\n"
        : "+f"(acc[0]), "+f"(acc[1]), "+f"(acc[2]), "+f"(acc[3])
        : "r"(a0), "r"(a1), "r"(a2), "r"(a3), "r"(b0), "r"(b1));
}

__device__ __forceinline__ void bargrp(int id) {
    asm volatile("bar.sync %0, 128;" :: "r"(id) : "memory");
}

__global__ void __launch_bounds__(512, 1)
win_attn_kernel(const float* __restrict__ x,
                const float* __restrict__ wqkv,
                const float* __restrict__ bqkv,
                const float* __restrict__ wproj,
                const float* __restrict__ bproj,
                float* __restrict__ out)
{
    extern __shared__ float smem[];
    float* Xs = smem + OFF_X;
    float* Qs = smem + OFF_Q;   // reused for O
    float* Ks = smem + OFF_K;
    float* Vs = smem + OFF_V;
    float* Ws = smem + OFF_W;
    float* Ss = smem + OFF_S;
    float* Pm = smem + OFF_PM;

    const int tid   = threadIdx.x;
    const int warp  = tid >> 5;
    const int lane  = tid & 31;
    const int g     = lane >> 2;
    const int t     = lane & 3;
    const int wr    = warp & 3;
    const int wc    = warp >> 2;       // 0..3
    const int mrow  = wr * 16;
    const int nbase = wc * 32;

    const float* xw = x + (size_t)blockIdx.x * 64 * 128;

    // ---------- prologue: X -> smem, stage W chunk0 ----------
    {
        float4 xs4[4];
        #pragma unroll
        for (int s = 0; s < 4; ++s) {
            int i = tid + s * 512;
            xs4[s] = *(const float4*)(xw + (i >> 5) * 128 + ((i & 31) << 2));
        }
        #pragma unroll
        for (int s = 0; s < 4; ++s) {
            int i = tid + s * 512;
            float* d = Xs + (i >> 5) * PX + ((i & 31) << 2);
            d[0] = tf32f(xs4[s].x); d[1] = tf32f(xs4[s].y);
            d[2] = tf32f(xs4[s].z); d[3] = tf32f(xs4[s].w);
        }
    }
    {
        float4 ws4[8];
        #pragma unroll
        for (int s = 0; s < 8; ++s) {
            int i = tid + s * 512;
            ws4[s] = *(const float4*)(wqkv + (i >> 5) * 384 + ((i & 31) << 2));
        }
        #pragma unroll
        for (int s = 0; s < 8; ++s) {
            int i = tid + s * 512;
            float* d = Ws + (i >> 5) * PW + ((i & 31) << 2);
            d[0] = tf32f(ws4[s].x); d[1] = tf32f(ws4[s].y);
            d[2] = tf32f(ws4[s].z); d[3] = tf32f(ws4[s].w);
        }
    }
    __syncthreads();

    // ============ GEMM1: QKV = X @ Wqkv + b, 3 chunks of 128 cols ============
    #pragma unroll
    for (int c = 0; c < 3; ++c) {
        // stage next chunk into regs early (hide L2 latency under MMAs)
        float4 ws4[8];
        if (c < 2) {
            #pragma unroll
            for (int s = 0; s < 8; ++s) {
                int i = tid + s * 512;
                ws4[s] = *(const float4*)(wqkv + (i >> 5) * 384 + (c + 1) * 128 + ((i & 31) << 2));
            }
        }

        float acc[4][4];
        #pragma unroll
        for (int n = 0; n < 4; ++n)
            acc[n][0] = acc[n][1] = acc[n][2] = acc[n][3] = 0.f;

        #pragma unroll
        for (int k0 = 0; k0 < 128; k0 += 8) {
            const float* xr = Xs + (mrow + g) * PX + k0 + t;
            uint32_t a0 = __float_as_uint(xr[0]);
            uint32_t a2 = __float_as_uint(xr[4]);
            uint32_t a1 = __float_as_uint(xr[8 * PX]);
            uint32_t a3 = __float_as_uint(xr[8 * PX + 4]);
            const float* wrp = Ws + (k0 + t) * PW + nbase + g;
            #pragma unroll
            for (int nt = 0; nt < 4; ++nt) {
                uint32_t b0 = __float_as_uint(wrp[nt * 8]);
                uint32_t b1 = __float_as_uint(wrp[4 * PW + nt * 8]);
                mma8(acc[nt], a0, a1, a2, a3, b0, b1);
            }
        }

        // epilogue: +bias, tf32-round, scatter to Q/K/V
        float* dst = (c == 0) ? Qs : ((c == 1) ? Ks : Vs);
        const int pad = (c == 2) ? PV : PX;
        #pragma unroll
        for (int nt = 0; nt < 4; ++nt) {
            int j = nbase + nt * 8 + 2 * t;
            float b0 = __ldg(bqkv + c * 128 + j);
            float b1 = __ldg(bqkv + c * 128 + j + 1);
            float2 v0 = make_float2(tf32f(acc[nt][0] + b0), tf32f(acc[nt][1] + b1));
            float2 v1 = make_float2(tf32f(acc[nt][2] + b0), tf32f(acc[nt][3] + b1));
            *(float2*)&dst[(mrow + g) * pad + j]     = v0;
            *(float2*)&dst[(mrow + g + 8) * pad + j] = v1;
        }
        __syncthreads();          // all warps done reading Ws for this chunk

        if (c < 2) {
            #pragma unroll
            for (int s = 0; s < 8; ++s) {
                int i = tid + s * 512;
                float* d = Ws + (i >> 5) * PW + ((i & 31) << 2);
                d[0] = tf32f(ws4[s].x); d[1] = tf32f(ws4[s].y);
                d[2] = tf32f(ws4[s].z); d[3] = tf32f(ws4[s].w);
            }
            __syncthreads();
        }
    }

    // ============ GEMM2: S = Q @ K^T (16 rows x 16 cols per warp) ============
    float sacc[2][4];
    #pragma unroll
    for (int n = 0; n < 2; ++n)
        sacc[n][0] = sacc[n][1] = sacc[n][2] = sacc[n][3] = 0.f;

    #pragma unroll
    for (int k0 = 0; k0 < 128; k0 += 8) {
        const float* qr = Qs + (mrow + g) * PX + k0 + t;
        uint32_t a0 = __float_as_uint(qr[0]);
        uint32_t a2 = __float_as_uint(qr[4]);
        uint32_t a1 = __float_as_uint(qr[8 * PX]);
        uint32_t a3 = __float_as_uint(qr[8 * PX + 4]);
        #pragma unroll
        for (int nt = 0; nt < 2; ++nt) {
            const float* kr = Ks + (wc * 16 + nt * 8 + g) * PX + k0 + t;
            uint32_t b0 = __float_as_uint(kr[0]);
            uint32_t b1 = __float_as_uint(kr[4]);
            mma8(sacc[nt], a0, a1, a2, a3, b0, b1);
        }
    }

    // ---------- softmax: each row spans the 4 warps with same wr ----------
    const float scale = 0.08838834764831844f;  // 128^-0.5
    const int bid = 1 + wr;
    float mx0 = -1e30f, mx1 = -1e30f;
    #pragma unroll
    for (int nt = 0; nt < 2; ++nt) {
        sacc[nt][0] *= scale; sacc[nt][1] *= scale;
        sacc[nt][2] *= scale; sacc[nt][3] *= scale;
        mx0 = fmaxf(mx0, fmaxf(sacc[nt][0], sacc[nt][1]));
        mx1 = fmaxf(mx1, fmaxf(sacc[nt][2], sacc[nt][3]));
    }
    mx0 = fmaxf(mx0, __shfl_xor_sync(0xffffffffu, mx0, 1));
    mx0 = fmaxf(mx0, __shfl_xor_sync(0xffffffffu, mx0, 2));
    mx1 = fmaxf(mx1, __shfl_xor_sync(0xffffffffu, mx1, 1));
    mx1 = fmaxf(mx1, __shfl_xor_sync(0xffffffffu, mx1, 2));
    if (t == 0) {
        Pm[(mrow + g) * 4 + wc]     = mx0;
        Pm[(mrow + g + 8) * 4 + wc] = mx1;
    }
    bargrp(bid);
    {
        const float* p0 = Pm + (mrow + g) * 4;
        const float* p1 = Pm + (mrow + g + 8) * 4;
        mx0 = fmaxf(fmaxf(p0[0], p0[1]), fmaxf(p0[2], p0[3]));
        mx1 = fmaxf(fmaxf(p1[0], p1[1]), fmaxf(p1[2], p1[3]));
    }

    float s0 = 0.f, s1 = 0.f;
    #pragma unroll
    for (int nt = 0; nt < 2; ++nt) {
        float p0 = __expf(sacc[nt][0] - mx0);
        float p1 = __expf(sacc[nt][1] - mx0);
        float p2 = __expf(sacc[nt][2] - mx1);
        float p3 = __expf(sacc[nt][3] - mx1);
        sacc[nt][0] = p0; sacc[nt][1] = p1; sacc[nt][2] = p2; sacc[nt][3] = p3;
        s0 += p0 + p1; s1 += p2 + p3;
    }
    s0 += __shfl_xor_sync(0xffffffffu, s0, 1);
    s0 += __shfl_xor_sync(0xffffffffu, s0, 2);
    s1 += __shfl_xor_sync(0xffffffffu, s1, 1);
    s1 += __shfl_xor_sync(0xffffffffu, s1, 2);
    if (t == 0) {
        Pm[256 + (mrow + g) * 4 + wc]     = s0;
        Pm[256 + (mrow + g + 8) * 4 + wc] = s1;
    }
    bargrp(bid);
    float r0, r1;
    {
        const float* p0 = Pm + 256 + (mrow + g) * 4;
        const float* p1 = Pm + 256 + (mrow + g + 8) * 4;
        r0 = 1.f / (p0[0] + p0[1] + p0[2] + p0[3]);
        r1 = 1.f / (p1[0] + p1[1] + p1[2] + p1[3]);
    }

    #pragma unroll
    for (int nt = 0; nt < 2; ++nt) {
        int j = wc * 16 + nt * 8 + 2 * t;
        float2 v0 = make_float2(tf32f(sacc[nt][0] * r0), tf32f(sacc[nt][1] * r0));
        float2 v1 = make_float2(tf32f(sacc[nt][2] * r1), tf32f(sacc[nt][3] * r1));
        *(float2*)&Ss[(mrow + g) * PS + j]     = v0;
        *(float2*)&Ss[(mrow + g + 8) * PS + j] = v1;
    }
    bargrp(bid);   // this wr-group's S rows complete

    // ============ GEMM3: O = P @ V (16 rows x 32 cols per warp) ============
    float oacc[4][4];
    #pragma unroll
    for (int n = 0; n < 4; ++n)
        oacc[n][0] = oacc[n][1] = oacc[n][2] = oacc[n][3] = 0.f;

    #pragma unroll
    for (int k0 = 0; k0 < 64; k0 += 8) {
        const float* pr = Ss + (mrow + g) * PS + k0 + t;
        uint32_t a0 = __float_as_uint(pr[0]);
        uint32_t a2 = __float_as_uint(pr[4]);
        uint32_t a1 = __float_as_uint(pr[8 * PS]);
        uint32_t a3 = __float_as_uint(pr[8 * PS + 4]);
        const float* vr = Vs + (k0 + t) * PV + nbase + g;
        #pragma unroll
        for (int nt = 0; nt < 4; ++nt) {
            uint32_t b0 = __float_as_uint(vr[nt * 8]);
            uint32_t b1 = __float_as_uint(vr[4 * PV + nt * 8]);
            mma8(oacc[nt], a0, a1, a2, a3, b0, b1);
        }
    }

    // store O into Qs (Q dead after GEMM2)
    #pragma unroll
    for (int nt = 0; nt < 4; ++nt) {
        int j = nbase + nt * 8 + 2 * t;
        float2 v0 = make_float2(tf32f(oacc[nt][0]), tf32f(oacc[nt][1]));
        float2 v1 = make_float2(tf32f(oacc[nt][2]), tf32f(oacc[nt][3]));
        *(float2*)&Qs[(mrow + g) * PX + j]     = v0;
        *(float2*)&Qs[(mrow + g + 8) * PX + j] = v1;
    }

    // stage wproj into regs (S region must not be overwritten until all read it)
    float4 ws4[8];
    #pragma unroll
    for (int s = 0; s < 8; ++s) {
        int i = tid + s * 512;
        ws4[s] = *(const float4*)(wproj + (i >> 5) * 128 + ((i & 31) << 2));
    }
    __syncthreads();               // all S reads + O writes done
    #pragma unroll
    for (int s = 0; s < 8; ++s) {
        int i = tid + s * 512;
        float* d = Ws + (i >> 5) * PW + ((i & 31) << 2);
        d[0] = tf32f(ws4[s].x); d[1] = tf32f(ws4[s].y);
        d[2] = tf32f(ws4[s].z); d[3] = tf32f(ws4[s].w);
    }
    __syncthreads();

    // ============ GEMM4: out = O @ Wproj + b ============
    float acc[4][4];
    #pragma unroll
    for (int n = 0; n < 4; ++n)
        acc[n][0] = acc[n][1] = acc[n][2] = acc[n][3] = 0.f;

    #pragma unroll
    for (int k0 = 0; k0 < 128; k0 += 8) {
        const float* orow = Qs + (mrow + g) * PX + k0 + t;
        uint32_t a0 = __float_as_uint(orow[0]);
        uint32_t a2 = __float_as_uint(orow[4]);
        uint32_t a1 = __float_as_uint(orow[8 * PX]);
        uint32_t a3 = __float_as_uint(orow[8 * PX + 4]);
        const float* wrp = Ws + (k0 + t) * PW + nbase + g;
        #pragma unroll
        for (int nt = 0; nt < 4; ++nt) {
            uint32_t b0 = __float_as_uint(wrp[nt * 8]);
            uint32_t b1 = __float_as_uint(wrp[4 * PW + nt * 8]);
            mma8(acc[nt], a0, a1, a2, a3, b0, b1);
        }
    }

    float* outw = out + (size_t)blockIdx.x * 64 * 128;
    #pragma unroll
    for (int nt = 0; nt < 4; ++nt) {
        int j = nbase + nt * 8 + 2 * t;
        float b0 = __ldg(bproj + j);
        float b1 = __ldg(bproj + j + 1);
        *(float2*)(outw + (mrow + g) * 128 + j) =
            make_float2(acc[nt][0] + b0, acc[nt][1] + b1);
        *(float2*)(outw + (mrow + g + 8) * 128 + j) =
            make_float2(acc[nt][2] + b0, acc[nt][3] + b1);
    }
}

extern "C" void kernel_launch(void* const* d_in, const int* in_sizes, int n_in,
                              void* d_out, int out_size)
{
    const float* x     = (const float*)d_in[0];
    const float* wqkv  = (const float*)d_in[1];
    const float* bqkv  = (const float*)d_in[2];
    const float* wproj = (const float*)d_in[3];
    const float* bproj = (const float*)d_in[4];
    float* out = (float*)d_out;

    const int nwin = in_sizes[0] / (64 * 128);  // 4096

    cudaFuncSetAttribute(win_attn_kernel,
                         cudaFuncAttributeMaxDynamicSharedMemorySize, SMEM_BYTES);

    win_attn_kernel<<<nwin, 512, SMEM_BYTES>>>(x, wqkv, bqkv, wproj, bproj, out);
}